// round 8
// baseline (speedup 1.0000x reference)
#include <cuda_runtime.h>
#include <math.h>

#define BB   16
#define NN   16000
#define GG   128
#define NPG  (NN + GG)          /* 16128 */
#define IMGW 800.0f
#define IMGH 800.0f
#define XCLIP 4.135166556742356f   /* log(1000/16) */
#define MAXWH 64.0f             /* boxes are at most 64px wide/tall */

#define NBX   12
#define NBINS (NBX * NBX)
#define BINW_INV (12.0f / 800.0f)

#define IPB    512              /* items (proposals) per block */
#define GRID_X 32               /* 32*512 = 16384 >= 16128 */

// Per-GT argmax keys: (q_bits<<32) | (0xFFFFFFFF - idx).
// Zero at module load == "no hit"; epilogue consumes AND re-zeroes each call
// so every graph replay starts clean.
__device__ unsigned long long g_keys[BB * GG];

__device__ __forceinline__ float4 ld4(const float* p) {
    return *reinterpret_cast<const float4*>(p);
}

// ---------------------------------------------------------------------------
// Main kernel: 2 proposals per thread (one wave, amortized prologue).
// decode+clip (fast math), labels + per-GT argmax (exact IoU via atomicMax).
// ---------------------------------------------------------------------------
__global__ void __launch_bounds__(256)
main_kernel(const float* __restrict__ props,
            const float* __restrict__ gts,
            const float* __restrict__ reg,
            float* __restrict__ out_pred,
            float* __restrict__ out_labels) {
    __shared__ float4       sg[GG];
    __shared__ float        sa[GG];
    __shared__ unsigned int smask[NBINS * 4];

    const int b   = blockIdx.y;
    const int tid = threadIdx.x;
    const float* gt_b = gts + (size_t)b * GG * 4;

    for (int i = tid; i < NBINS * 4; i += 256) smask[i] = 0u;
    __syncthreads();

    // ---- prologue: GT boxes -> smem + corner-bin masks (dilated 64px) ----
    if (tid < GG) {
        float4 v = ld4(gt_b + tid * 4);
        sg[tid] = v;
        sa[tid] = __fmul_rn(__fsub_rn(v.z, v.x), __fsub_rn(v.w, v.y));
        int bx0 = (int)(fmaxf(v.x - MAXWH, 0.0f) * BINW_INV);
        int bx1 = (int)(v.z * BINW_INV); if (bx1 > NBX - 1) bx1 = NBX - 1;
        int by0 = (int)(fmaxf(v.y - MAXWH, 0.0f) * BINW_INV);
        int by1 = (int)(v.w * BINW_INV); if (by1 > NBX - 1) by1 = NBX - 1;
        const unsigned bit  = 1u << (tid & 31);
        const int      word = tid >> 5;
        for (int by = by0; by <= by1; by++)
            for (int bx = bx0; bx <= bx1; bx++)
                atomicOr(&smask[(by * NBX + bx) * 4 + word], bit);
    }
    __syncthreads();

    unsigned long long* keyrow = g_keys + b * GG;

#pragma unroll
    for (int it = 0; it < 2; it++) {
        const int p = blockIdx.x * IPB + it * 256 + tid;
        if (p >= NPG) break;                 // only block 31, item 2
        const bool isprop = (p < NN);

        float4 a = isprop ? ld4(props + ((size_t)b * NN + p) * 4) : sg[p - NN];

        // ---- decode + clip (outputs only: fast math) ----
        {
            float4 r = ld4(reg + ((size_t)b * NPG + p) * 4);
            float pw  = a.z - a.x;
            float ph  = a.w - a.y;
            float pcx = fmaf(0.5f, pw, a.x);
            float pcy = fmaf(0.5f, ph, a.y);
            float dx = r.x * 0.1f;
            float dy = r.y * 0.1f;
            float dw = fminf(r.z * 0.2f, XCLIP);
            float dh = fminf(r.w * 0.2f, XCLIP);
            float ncx = fmaf(dx, pw, pcx);
            float ncy = fmaf(dy, ph, pcy);
            float hnw = 0.5f * __expf(dw) * pw;
            float hnh = 0.5f * __expf(dh) * ph;
            float4 o;
            o.x = fminf(fmaxf(ncx - hnw, 0.0f), IMGW);
            o.y = fminf(fmaxf(ncy - hnh, 0.0f), IMGH);
            o.z = fminf(fmaxf(ncx + hnw, 0.0f), IMGW);
            o.w = fminf(fmaxf(ncy + hnh, 0.0f), IMGH);
            *reinterpret_cast<float4*>(out_pred + ((size_t)b * NPG + p) * 4) = o;
        }

        // ---- labels + argmax (exact IoU) ----
        float label;
        if (!isprop) {
            label = 1.0f;   // appended GT: self-IoU == 1.0
        } else {
            const float area_a =
                __fmul_rn(__fsub_rn(a.z, a.x), __fsub_rn(a.w, a.y));
            float vmax = 0.0f;
            const unsigned low = 0xFFFFFFFFu - (unsigned)p;

            const int bin = (int)(a.y * BINW_INV) * NBX + (int)(a.x * BINW_INV);
            uint4 m4 = *reinterpret_cast<const uint4*>(&smask[bin * 4]);
            unsigned mw[4] = {m4.x, m4.y, m4.z, m4.w};

#pragma unroll
            for (int w = 0; w < 4; w++) {
                unsigned m = mw[w];
                while (m) {
                    int g = (w << 5) + (__ffs(m) - 1);
                    m &= m - 1;
                    float4 gb = sg[g];
                    float ltx = fmaxf(a.x, gb.x);
                    float lty = fmaxf(a.y, gb.y);
                    float rbx = fminf(a.z, gb.z);
                    float rby = fminf(a.w, gb.w);
                    float ww = __fsub_rn(rbx, ltx);
                    float hh = __fsub_rn(rby, lty);
                    if (ww > 0.0f && hh > 0.0f) {
                        float inter = __fmul_rn(ww, hh);
                        float uni   = __fsub_rn(__fadd_rn(sa[g], area_a), inter);
                        float q     = __fdiv_rn(inter, uni);
                        vmax = fmaxf(vmax, q);
                        unsigned long long key =
                            ((unsigned long long)__float_as_uint(q) << 32) | low;
                        atomicMax(keyrow + g, key);
                    }
                }
            }
            label = (vmax >= 0.5f) ? 1.0f : 0.0f;
        }
        out_labels[(size_t)b * NPG + p] = label;
    }
}

// ---------------------------------------------------------------------------
// Epilogue: keys -> reg_targets + roi_scores; resets keys for next replay.
// ---------------------------------------------------------------------------
__global__ void __launch_bounds__(256)
epilogue_kernel(const float* __restrict__ props,
                const float* __restrict__ gts,
                float* __restrict__ out_regt,
                float* __restrict__ out_scores) {
    int i = blockIdx.x * 256 + threadIdx.x;
    if (i >= BB * GG) return;
    int b = i >> 7;
    int g = i & (GG - 1);

    unsigned long long key = __ldcg(&g_keys[i]);
    __stcg(&g_keys[i], 0ull);              // reset for next graph replay
    float q = __uint_as_float((unsigned)(key >> 32));
    unsigned idx = (key == 0ull) ? 0u
                 : (0xFFFFFFFFu - (unsigned)(key & 0xFFFFFFFFull));

    float4 mp = ld4(props + ((size_t)b * NN + idx) * 4);
    float4 gb = ld4(gts + ((size_t)b * GG + g) * 4);

    float pw  = mp.z - mp.x;
    float ph  = mp.w - mp.y;
    float pcx = fmaf(0.5f, pw, mp.x);
    float pcy = fmaf(0.5f, ph, mp.y);
    float gw  = gb.z - gb.x;
    float gh  = gb.w - gb.y;
    float gcx = fmaf(0.5f, gw, gb.x);
    float gcy = fmaf(0.5f, gh, gb.y);

    float dx = __fdividef(10.0f * (gcx - pcx), pw);
    float dy = __fdividef(10.0f * (gcy - pcy), ph);
    float dw = 5.0f * __logf(__fdividef(gw, pw));
    float dh = 5.0f * __logf(__fdividef(gh, ph));

    float* o = out_regt + (size_t)i * 4;
    o[0] = dx; o[1] = dy; o[2] = dw; o[3] = dh;
    out_scores[i] = q;
}

// ---------------------------------------------------------------------------
extern "C" void kernel_launch(void* const* d_in, const int* in_sizes, int n_in,
                              void* d_out, int out_size) {
    const float* props = (const float*)d_in[0];   // (B, N, 4)
    const float* gts   = (const float*)d_in[1];   // (B, G, 4)
    const float* reg   = (const float*)d_in[2];   // (B, N+G, 4)

    float* out        = (float*)d_out;
    float* out_pred   = out;                                  // B*(N+G)*4
    float* out_regt   = out_pred + (size_t)BB * NPG * 4;      // B*G*4
    float* out_scores = out_regt + (size_t)BB * GG * 4;       // B*G
    float* out_labels = out_scores + (size_t)BB * GG;         // B*(N+G)

    dim3 gm(GRID_X, BB);
    main_kernel<<<gm, 256>>>(props, gts, reg, out_pred, out_labels);

    epilogue_kernel<<<(BB * GG + 255) / 256, 256>>>(props, gts,
                                                    out_regt, out_scores);
}

// round 9
// speedup vs baseline: 1.3756x; 1.3756x over previous
#include <cuda_runtime.h>
#include <math.h>

#define BB   16
#define NN   16000
#define GG   128
#define NPG  (NN + GG)          /* 16128 = 63 * 256 exactly */
#define IMGW 800.0f
#define IMGH 800.0f
#define XCLIP 4.135166556742356f   /* log(1000/16) */
#define MAXWH 64.0f             /* boxes are at most 64px wide/tall */

#define NBX   12
#define NBINS (NBX * NBX)
#define BINW_INV (12.0f / 800.0f)

#define GRID_X (NPG / 256)      /* 63 */

// Per-GT argmax keys: (q_bits<<32) | (0xFFFFFFFF - idx).
// Zero at module load == "no hit"; kernel2 consumes AND re-zeroes each call
// so every graph replay starts clean.
__device__ unsigned long long g_keys[BB * GG];

__device__ __forceinline__ float4 ld4(const float* p) {
    return *reinterpret_cast<const float4*>(p);
}

// ---------------------------------------------------------------------------
// Kernel 1: IoU only — labels + per-GT argmax (exact IoU via atomicMax).
// Slim register footprint -> 8 blocks/SM -> 64 resident warps (latency-bound
// loop gets maximum hiding).
// ---------------------------------------------------------------------------
__global__ void __launch_bounds__(256)
iou_kernel(const float* __restrict__ props,
           const float* __restrict__ gts,
           float* __restrict__ out_labels) {
    __shared__ float4       sg[GG];
    __shared__ float        sa[GG];
    __shared__ unsigned int smask[NBINS * 4];

    const int b   = blockIdx.y;
    const int tid = threadIdx.x;
    const float* gt_b = gts + (size_t)b * GG * 4;

    for (int i = tid; i < NBINS * 4; i += 256) smask[i] = 0u;
    __syncthreads();

    // ---- prologue: GT boxes -> smem + corner-bin masks (dilated 64px) ----
    if (tid < GG) {
        float4 v = ld4(gt_b + tid * 4);
        sg[tid] = v;
        sa[tid] = __fmul_rn(__fsub_rn(v.z, v.x), __fsub_rn(v.w, v.y));
        int bx0 = (int)(fmaxf(v.x - MAXWH, 0.0f) * BINW_INV);
        int bx1 = (int)(v.z * BINW_INV); if (bx1 > NBX - 1) bx1 = NBX - 1;
        int by0 = (int)(fmaxf(v.y - MAXWH, 0.0f) * BINW_INV);
        int by1 = (int)(v.w * BINW_INV); if (by1 > NBX - 1) by1 = NBX - 1;
        const unsigned bit  = 1u << (tid & 31);
        const int      word = tid >> 5;
        for (int by = by0; by <= by1; by++)
            for (int bx = bx0; bx <= bx1; bx++)
                atomicOr(&smask[(by * NBX + bx) * 4 + word], bit);
    }
    __syncthreads();

    const int p = blockIdx.x * 256 + tid;   // grid sized exactly, p < NPG

    float label;
    if (p >= NN) {
        label = 1.0f;   // appended GT: self-IoU == 1.0, not in argmax domain
    } else {
        float4 a = ld4(props + ((size_t)b * NN + p) * 4);
        const float area_a = __fmul_rn(__fsub_rn(a.z, a.x), __fsub_rn(a.w, a.y));
        float vmax = 0.0f;
        unsigned long long* keyrow = g_keys + b * GG;
        const unsigned low = 0xFFFFFFFFu - (unsigned)p;

        const int bin = (int)(a.y * BINW_INV) * NBX + (int)(a.x * BINW_INV);
        uint4 m4 = *reinterpret_cast<const uint4*>(&smask[bin * 4]);
        unsigned mw[4] = {m4.x, m4.y, m4.z, m4.w};

#pragma unroll
        for (int w = 0; w < 4; w++) {
            unsigned m = mw[w];
            while (m) {
                int g = (w << 5) + (__ffs(m) - 1);
                m &= m - 1;
                float4 gb = sg[g];
                float ltx = fmaxf(a.x, gb.x);
                float lty = fmaxf(a.y, gb.y);
                float rbx = fminf(a.z, gb.z);
                float rby = fminf(a.w, gb.w);
                float ww = __fsub_rn(rbx, ltx);
                float hh = __fsub_rn(rby, lty);
                if (ww > 0.0f && hh > 0.0f) {
                    float inter = __fmul_rn(ww, hh);
                    float uni   = __fsub_rn(__fadd_rn(sa[g], area_a), inter);
                    float q     = __fdiv_rn(inter, uni);
                    vmax = fmaxf(vmax, q);
                    unsigned long long key =
                        ((unsigned long long)__float_as_uint(q) << 32) | low;
                    atomicMax(keyrow + g, key);
                }
            }
        }
        label = (vmax >= 0.5f) ? 1.0f : 0.0f;
    }
    out_labels[(size_t)b * NPG + p] = label;
}

// ---------------------------------------------------------------------------
// Kernel 2: decode+clip for all B*(N+G) boxes; additionally, its first 8
// blocks (y==0, x<8) run the 2048-item encode epilogue (keys -> reg_targets
// + roi_scores, then key reset). No third launch.
// ---------------------------------------------------------------------------
__global__ void __launch_bounds__(256)
decode_kernel(const float* __restrict__ props,
              const float* __restrict__ gts,
              const float* __restrict__ reg,
              float* __restrict__ out_pred,
              float* __restrict__ out_regt,
              float* __restrict__ out_scores) {
    const int b   = blockIdx.y;
    const int tid = threadIdx.x;
    const int p   = blockIdx.x * 256 + tid;

    // ---- decode + clip (outputs only: fast math) ----
    {
        float4 a = (p < NN) ? ld4(props + ((size_t)b * NN + p) * 4)
                            : ld4(gts + ((size_t)b * GG + (p - NN)) * 4);
        float4 r = ld4(reg + ((size_t)b * NPG + p) * 4);
        float pw  = a.z - a.x;
        float ph  = a.w - a.y;
        float pcx = fmaf(0.5f, pw, a.x);
        float pcy = fmaf(0.5f, ph, a.y);
        float dx = r.x * 0.1f;
        float dy = r.y * 0.1f;
        float dw = fminf(r.z * 0.2f, XCLIP);
        float dh = fminf(r.w * 0.2f, XCLIP);
        float ncx = fmaf(dx, pw, pcx);
        float ncy = fmaf(dy, ph, pcy);
        float hnw = 0.5f * __expf(dw) * pw;
        float hnh = 0.5f * __expf(dh) * ph;
        float4 o;
        o.x = fminf(fmaxf(ncx - hnw, 0.0f), IMGW);
        o.y = fminf(fmaxf(ncy - hnh, 0.0f), IMGH);
        o.z = fminf(fmaxf(ncx + hnw, 0.0f), IMGW);
        o.w = fminf(fmaxf(ncy + hnh, 0.0f), IMGH);
        *reinterpret_cast<float4*>(out_pred + ((size_t)b * NPG + p) * 4) = o;
    }

    // ---- encode epilogue, folded into the first 8 blocks ----
    if (blockIdx.y == 0 && blockIdx.x < 8) {
        int i  = blockIdx.x * 256 + tid;     // i < 2048 = BB*GG
        int bb = i >> 7;
        int g  = i & (GG - 1);

        unsigned long long key = __ldcg(&g_keys[i]);
        __stcg(&g_keys[i], 0ull);            // reset for next graph replay
        float q = __uint_as_float((unsigned)(key >> 32));
        unsigned idx = (key == 0ull) ? 0u
                     : (0xFFFFFFFFu - (unsigned)(key & 0xFFFFFFFFull));

        float4 mp = ld4(props + ((size_t)bb * NN + idx) * 4);
        float4 gb = ld4(gts + ((size_t)bb * GG + g) * 4);

        float pw  = mp.z - mp.x;
        float ph  = mp.w - mp.y;
        float pcx = fmaf(0.5f, pw, mp.x);
        float pcy = fmaf(0.5f, ph, mp.y);
        float gw  = gb.z - gb.x;
        float gh  = gb.w - gb.y;
        float gcx = fmaf(0.5f, gw, gb.x);
        float gcy = fmaf(0.5f, gh, gb.y);

        float dx = __fdividef(10.0f * (gcx - pcx), pw);
        float dy = __fdividef(10.0f * (gcy - pcy), ph);
        float dw = 5.0f * __logf(__fdividef(gw, pw));
        float dh = 5.0f * __logf(__fdividef(gh, ph));

        float* o = out_regt + (size_t)i * 4;
        o[0] = dx; o[1] = dy; o[2] = dw; o[3] = dh;
        out_scores[i] = q;
    }
}

// ---------------------------------------------------------------------------
extern "C" void kernel_launch(void* const* d_in, const int* in_sizes, int n_in,
                              void* d_out, int out_size) {
    const float* props = (const float*)d_in[0];   // (B, N, 4)
    const float* gts   = (const float*)d_in[1];   // (B, G, 4)
    const float* reg   = (const float*)d_in[2];   // (B, N+G, 4)

    float* out        = (float*)d_out;
    float* out_pred   = out;                                  // B*(N+G)*4
    float* out_regt   = out_pred + (size_t)BB * NPG * 4;      // B*G*4
    float* out_scores = out_regt + (size_t)BB * GG * 4;       // B*G
    float* out_labels = out_scores + (size_t)BB * GG;         // B*(N+G)

    dim3 gm(GRID_X, BB);
    iou_kernel<<<gm, 256>>>(props, gts, out_labels);

    decode_kernel<<<gm, 256>>>(props, gts, reg,
                               out_pred, out_regt, out_scores);
}